// round 4
// baseline (speedup 1.0000x reference)
#include <cuda_runtime.h>

#define Bb 4
#define Tt 128
#define Ss 512
#define Hh 512

// Scratch (no allocations allowed -> __device__ globals).
__device__ float g_pq[Bb * Tt * Hh];          // query @ W_s
__device__ float g_pe[Bb * Ss * Hh];          // encoder @ W_h
__device__ float g_cat[Bb * Tt * 2 * Hh];     // [context | query]

__device__ __forceinline__ float tanh_fast(float x) {
    float y;
    asm("tanh.approx.f32 %0, %1;" : "=f"(y) : "f"(x));
    return y;
}

// ---------------------------------------------------------------------------
// 64x64-tile SGEMM, C[M,N] = A[M,K] @ B[K,N]. M%64==0, N%64==0, K%16==0.
// 256 threads, each computes a 4x4 micro-tile.
// A_SRC: 0=Ap param, 1=g_cat.  C_DST: 0=Cp param, 1=g_pq, 2=g_pe.
// DO_TANH applies tanh.approx to the output.
// ---------------------------------------------------------------------------
template <int A_SRC, int C_DST, int DO_TANH>
__global__ __launch_bounds__(256) void sgemm64(
    const float* __restrict__ Ap, const float* __restrict__ Bm,
    float* __restrict__ Cp, int M, int N, int K)
{
    const float* __restrict__ A =
        (A_SRC == 1) ? (const float*)g_cat : Ap;
    float* __restrict__ C =
        (C_DST == 1) ? (float*)g_pq : (C_DST == 2) ? (float*)g_pe : Cp;

    __shared__ float As[16][68];
    __shared__ float Bs[16][68];
    const int tid = threadIdx.x;
    const int tx = tid & 15;
    const int ty = tid >> 4;
    const int rowBase = blockIdx.y << 6;
    const int colBase = blockIdx.x << 6;
    const int la_r = tid >> 2;            // 0..63
    const int la_k = (tid & 3) << 2;      // 0,4,8,12
    const int lb_k = tid >> 4;            // 0..15
    const int lb_c = (tid & 15) << 2;     // 0..60

    float acc[4][4] = {};

    for (int kt = 0; kt < K; kt += 16) {
        float4 av = *(const float4*)(A + (size_t)(rowBase + la_r) * K + kt + la_k);
        As[la_k + 0][la_r] = av.x;
        As[la_k + 1][la_r] = av.y;
        As[la_k + 2][la_r] = av.z;
        As[la_k + 3][la_r] = av.w;
        float4 bv = *(const float4*)(Bm + (size_t)(kt + lb_k) * N + colBase + lb_c);
        *(float4*)&Bs[lb_k][lb_c] = bv;
        __syncthreads();
        #pragma unroll
        for (int k = 0; k < 16; ++k) {
            float ar[4], br[4];
            #pragma unroll
            for (int i = 0; i < 4; ++i) ar[i] = As[k][(ty << 2) + i];
            #pragma unroll
            for (int j = 0; j < 4; ++j) br[j] = Bs[k][(tx << 2) + j];
            #pragma unroll
            for (int i = 0; i < 4; ++i)
                #pragma unroll
                for (int j = 0; j < 4; ++j)
                    acc[i][j] = fmaf(ar[i], br[j], acc[i][j]);
        }
        __syncthreads();
    }

    #pragma unroll
    for (int i = 0; i < 4; ++i) {
        const int r = rowBase + (ty << 2) + i;
        #pragma unroll
        for (int j = 0; j < 4; ++j) {
            float o = acc[i][j];
            if (DO_TANH) o = tanh_fast(o);
            C[(size_t)r * N + colBase + (tx << 2) + j] = o;
        }
    }
}

// ---------------------------------------------------------------------------
// Fused score + masked softmax + context per (b,t).
// grid = (T, B), 256 threads; thread handles s = tid and s = tid+256,
// then h = tid and h = tid+256 for the context accumulation.
// ---------------------------------------------------------------------------
__global__ __launch_bounds__(256) void score_ctx_kernel(
    const float* __restrict__ query,
    const float* __restrict__ enc,
    const float* __restrict__ v,
    const int* __restrict__ src_len)
{
    const int t = blockIdx.x;
    const int b = blockIdx.y;
    const int tid = threadIdx.x;

    __shared__ float pq_s[Hh];
    __shared__ float v_s[Hh];
    __shared__ float sc[Ss];
    __shared__ float red[8];
    __shared__ float s_max, s_inv;

    const float* pqrow = g_pq + (size_t)(b * Tt + t) * Hh;
    for (int i = tid; i < Hh; i += 256) {
        pq_s[i] = pqrow[i];
        v_s[i]  = v[i];
    }
    __syncthreads();

    const int len = src_len[b];
    const int s0 = tid;
    const int s1 = tid + 256;
    const float NEGINF = __int_as_float(0xff800000);

    const float* pe0 = g_pe + (size_t)(b * Ss + s0) * Hh;
    const float* pe1 = pe0 + 256 * Hh;

    float acc0 = 0.f, acc1 = 0.f;
    if (s1 < len) {
        #pragma unroll 2
        for (int h = 0; h < Hh; h += 4) {
            float4 p  = *(const float4*)(pq_s + h);
            float4 vv = *(const float4*)(v_s + h);
            float4 e0 = *(const float4*)(pe0 + h);
            float4 e1 = *(const float4*)(pe1 + h);
            acc0 = fmaf(vv.x, tanh_fast(p.x + e0.x), acc0);
            acc1 = fmaf(vv.x, tanh_fast(p.x + e1.x), acc1);
            acc0 = fmaf(vv.y, tanh_fast(p.y + e0.y), acc0);
            acc1 = fmaf(vv.y, tanh_fast(p.y + e1.y), acc1);
            acc0 = fmaf(vv.z, tanh_fast(p.z + e0.z), acc0);
            acc1 = fmaf(vv.z, tanh_fast(p.z + e1.z), acc1);
            acc0 = fmaf(vv.w, tanh_fast(p.w + e0.w), acc0);
            acc1 = fmaf(vv.w, tanh_fast(p.w + e1.w), acc1);
        }
    } else if (s0 < len) {
        #pragma unroll 2
        for (int h = 0; h < Hh; h += 4) {
            float4 p  = *(const float4*)(pq_s + h);
            float4 vv = *(const float4*)(v_s + h);
            float4 e0 = *(const float4*)(pe0 + h);
            acc0 = fmaf(vv.x, tanh_fast(p.x + e0.x), acc0);
            acc0 = fmaf(vv.y, tanh_fast(p.y + e0.y), acc0);
            acc0 = fmaf(vv.z, tanh_fast(p.z + e0.z), acc0);
            acc0 = fmaf(vv.w, tanh_fast(p.w + e0.w), acc0);
        }
    }

    const float v0 = (s0 < len) ? acc0 : NEGINF;
    const float v1 = (s1 < len) ? acc1 : NEGINF;

    // ---- block max ----
    float m = fmaxf(v0, v1);
    #pragma unroll
    for (int o = 16; o; o >>= 1) m = fmaxf(m, __shfl_xor_sync(0xffffffffu, m, o));
    if ((tid & 31) == 0) red[tid >> 5] = m;
    __syncthreads();
    if (tid == 0) {
        float mm = red[0];
        #pragma unroll
        for (int i = 1; i < 8; ++i) mm = fmaxf(mm, red[i]);
        s_max = mm;
    }
    __syncthreads();
    const float mx = s_max;

    // ---- exp + sum ----
    float e0 = (s0 < len) ? __expf(v0 - mx) : 0.f;
    float e1 = (s1 < len) ? __expf(v1 - mx) : 0.f;
    float sum = e0 + e1;
    #pragma unroll
    for (int o = 16; o; o >>= 1) sum += __shfl_xor_sync(0xffffffffu, sum, o);
    __syncthreads();   // reuse of red[]
    if ((tid & 31) == 0) red[tid >> 5] = sum;
    __syncthreads();
    if (tid == 0) {
        float tot = red[0];
        #pragma unroll
        for (int i = 1; i < 8; ++i) tot += red[i];
        s_inv = 1.f / tot;
    }
    __syncthreads();
    const float inv = s_inv;
    sc[s0] = e0 * inv;
    sc[s1] = e1 * inv;
    __syncthreads();

    // ---- context: c[h] = sum_s alpha[s] * enc[b,s,h] ----
    const int h0 = tid;
    const int h1 = tid + 256;
    const float* eb = enc + (size_t)b * Ss * Hh;
    float c0 = 0.f, c1 = 0.f;
    #pragma unroll 4
    for (int s = 0; s < len; ++s) {
        const float a = sc[s];
        c0 = fmaf(a, eb[(size_t)s * Hh + h0], c0);
        c1 = fmaf(a, eb[(size_t)s * Hh + h1], c1);
    }

    float* crow = g_cat + (size_t)(b * Tt + t) * (2 * Hh);
    crow[h0] = c0;
    crow[h1] = c1;
    const float* qrow = query + (size_t)(b * Tt + t) * Hh;
    crow[Hh + h0] = qrow[h0];
    crow[Hh + h1] = qrow[h1];
}

// ---------------------------------------------------------------------------

extern "C" void kernel_launch(void* const* d_in, const int* in_sizes, int n_in,
                              void* d_out, int out_size)
{
    const float* query = (const float*)d_in[0];
    const float* enc   = (const float*)d_in[1];
    const int*   slen  = (const int*)d_in[2];
    const float* W_h   = (const float*)d_in[3];
    const float* W_s   = (const float*)d_in[4];
    const float* v     = (const float*)d_in[5];
    const float* W_out = (const float*)d_in[6];
    float* out = (float*)d_out;

    // pq = query @ W_s : (512,512)x(512,512) -> g_pq
    sgemm64<0, 1, 0><<<dim3(Hh / 64, (Bb * Tt) / 64), 256>>>(query, W_s, nullptr, Bb * Tt, Hh, Hh);
    // pe = enc @ W_h : (2048,512)x(512,512) -> g_pe
    sgemm64<0, 2, 0><<<dim3(Hh / 64, (Bb * Ss) / 64), 256>>>(enc, W_h, nullptr, Bb * Ss, Hh, Hh);
    // score + softmax + context (writes g_cat = [context | query])
    score_ctx_kernel<<<dim3(Tt, Bb), 256>>>(query, enc, v, slen);
    // out = tanh(g_cat @ W_out) : (512,1024)x(1024,512)
    sgemm64<1, 0, 1><<<dim3(Hh / 64, (Bb * Tt) / 64), 256>>>(nullptr, W_out, out, Bb * Tt, Hh, 2 * Hh);
}

// round 5
// speedup vs baseline: 1.5496x; 1.5496x over previous
#include <cuda_runtime.h>

#define Bb 4
#define Tt 128
#define Ss 512
#define Hh 512

// Scratch (no allocations allowed -> __device__ globals).
__device__ float g_pq[Bb * Tt * Hh];    // query @ W_s
__device__ float g_pe[Bb * Ss * Hh];    // encoder @ W_h
__device__ float g_pre[Bb * Tt * Hh];   // query @ W_out[H:2H]  (query part of output proj)
__device__ float g_ctx[Bb * Tt * Hh];   // attention context

__device__ __forceinline__ float tanh_fast(float x) {
    float y;
    asm("tanh.approx.f32 %0, %1;" : "=f"(y) : "f"(x));
    return y;
}

// ---------------------------------------------------------------------------
// Shared GEMM tile body: BM=32, BN=64, BK=32, 256 threads, 2x4 micro-tile.
// C tile (32x64) at (rowBase, colBase); A[M,K] row-major, B[K,N] row-major.
// ---------------------------------------------------------------------------
__device__ __forceinline__ void gemm_body(
    const float* __restrict__ A, const float* __restrict__ B,
    int K, int N, int rowBase, int colBase,
    float (*As)[34], float (*Bs)[68], float acc[2][4])
{
    const int tid = threadIdx.x;
    const int tx = tid & 15;        // 16 col-groups of 4
    const int ty = tid >> 4;        // 16 row-groups of 2
    const int ar = tid >> 3;        // A row within tile 0..31
    const int ak = (tid & 7) << 2;  // A k-offset 0..28
    const int bk = tid >> 3;        // B k-row 0..31
    const int bn = (tid & 7) << 3;  // B col-offset 0..56

    for (int kt = 0; kt < K; kt += 32) {
        float4 av = *(const float4*)(A + (size_t)(rowBase + ar) * K + kt + ak);
        const float* bp = B + (size_t)(kt + bk) * N + colBase + bn;
        float4 b0 = *(const float4*)bp;
        float4 b1 = *(const float4*)(bp + 4);
        As[ak + 0][ar] = av.x;
        As[ak + 1][ar] = av.y;
        As[ak + 2][ar] = av.z;
        As[ak + 3][ar] = av.w;
        *(float4*)&Bs[bk][bn]     = b0;
        *(float4*)&Bs[bk][bn + 4] = b1;
        __syncthreads();
        #pragma unroll
        for (int k = 0; k < 32; ++k) {
            float2 a  = *(const float2*)&As[k][ty << 1];
            float4 bb = *(const float4*)&Bs[k][tx << 2];
            acc[0][0] = fmaf(a.x, bb.x, acc[0][0]);
            acc[0][1] = fmaf(a.x, bb.y, acc[0][1]);
            acc[0][2] = fmaf(a.x, bb.z, acc[0][2]);
            acc[0][3] = fmaf(a.x, bb.w, acc[0][3]);
            acc[1][0] = fmaf(a.y, bb.x, acc[1][0]);
            acc[1][1] = fmaf(a.y, bb.y, acc[1][1]);
            acc[1][2] = fmaf(a.y, bb.z, acc[1][2]);
            acc[1][3] = fmaf(a.y, bb.w, acc[1][3]);
        }
        __syncthreads();
    }
}

// ---------------------------------------------------------------------------
// Phase 1: three GEMMs in one launch (linear tile index, 768 CTAs).
//   tiles [0,128):   g_pq  = query @ W_s          (512 x 512, K=512)
//   tiles [128,640): g_pe  = enc   @ W_h          (2048 x 512, K=512)
//   tiles [640,768): g_pre = query @ W_out[H:2H]  (512 x 512, K=512)
// ---------------------------------------------------------------------------
__global__ __launch_bounds__(256) void phase1_gemm(
    const float* __restrict__ query, const float* __restrict__ enc,
    const float* __restrict__ W_h, const float* __restrict__ W_s,
    const float* __restrict__ W_out)
{
    __shared__ float As[32][34];
    __shared__ float Bs[32][68];

    int id = blockIdx.x;
    const float* A;
    const float* B;
    float* C;
    if (id < 128)        { A = query; B = W_s; C = g_pq; }
    else if (id < 640)   { A = enc;   B = W_h; C = g_pe;  id -= 128; }
    else                 { A = query; B = W_out + Hh * Hh; C = g_pre; id -= 640; }

    const int rowBase = (id >> 3) << 5;   // 8 col-tiles of 64 across N=512
    const int colBase = (id & 7) << 6;

    float acc[2][4] = {};
    gemm_body(A, B, Hh, Hh, rowBase, colBase, As, Bs, acc);

    const int tx = threadIdx.x & 15;
    const int ty = threadIdx.x >> 4;
    const int r0 = rowBase + (ty << 1);
    const int c0 = colBase + (tx << 2);
    *(float4*)&C[(size_t)r0 * Hh + c0]       = make_float4(acc[0][0], acc[0][1], acc[0][2], acc[0][3]);
    *(float4*)&C[(size_t)(r0 + 1) * Hh + c0] = make_float4(acc[1][0], acc[1][1], acc[1][2], acc[1][3]);
}

// ---------------------------------------------------------------------------
// Final: out = tanh(g_ctx @ W_out[0:H] + g_pre).  128 CTAs.
// ---------------------------------------------------------------------------
__global__ __launch_bounds__(256) void final_gemm(
    const float* __restrict__ W_out, float* __restrict__ out)
{
    __shared__ float As[32][34];
    __shared__ float Bs[32][68];

    const int id = blockIdx.x;
    const int rowBase = (id >> 3) << 5;
    const int colBase = (id & 7) << 6;

    float acc[2][4] = {};
    gemm_body((const float*)g_ctx, W_out, Hh, Hh, rowBase, colBase, As, Bs, acc);

    const int tx = threadIdx.x & 15;
    const int ty = threadIdx.x >> 4;
    #pragma unroll
    for (int i = 0; i < 2; ++i) {
        const int r = rowBase + (ty << 1) + i;
        const int c = colBase + (tx << 2);
        float4 pre = *(const float4*)&g_pre[(size_t)r * Hh + c];
        float4 o;
        o.x = tanh_fast(acc[i][0] + pre.x);
        o.y = tanh_fast(acc[i][1] + pre.y);
        o.z = tanh_fast(acc[i][2] + pre.z);
        o.w = tanh_fast(acc[i][3] + pre.w);
        *(float4*)&out[(size_t)r * Hh + c] = o;
    }
}

// ---------------------------------------------------------------------------
// Score + masked softmax + context, 4 t-values per CTA.
// grid = (T/4, B), 256 threads. Each thread owns s = tid and s = tid+256 for
// scoring, then h = tid and h = tid+256 for the context accumulation.
// ---------------------------------------------------------------------------
__global__ __launch_bounds__(256) void score_ctx_kernel(
    const float* __restrict__ enc,
    const float* __restrict__ v,
    const int* __restrict__ src_len)
{
    const int b  = blockIdx.y;
    const int t0 = blockIdx.x << 2;
    const int tid = threadIdx.x;

    __shared__ float pq4[4 * Hh];      // 4 query projections (rows contiguous)
    __shared__ float v_s[Hh];
    __shared__ float alp[Ss][4];       // alignment, s-major
    __shared__ float4 red[8];
    __shared__ float4 bc;

    const float* pqb = g_pq + (size_t)(b * Tt + t0) * Hh;
    for (int i = tid; i < 4 * Hh; i += 256) pq4[i] = pqb[i];
    for (int i = tid; i < Hh; i += 256) v_s[i] = v[i];
    __syncthreads();

    const int len = src_len[b];
    const float NEGINF = __int_as_float(0xff800000);

    float sv0[4], sv1[4];

    // ---- scores for this thread's two s values ----
    #pragma unroll
    for (int half = 0; half < 2; ++half) {
        const int s = tid + (half << 8);
        float* sv = half ? sv1 : sv0;
        float a0 = 0.f, a1 = 0.f, a2 = 0.f, a3 = 0.f;
        if (s < len) {
            const float* pe = g_pe + (size_t)(b * Ss + s) * Hh;
            #pragma unroll 2
            for (int h = 0; h < Hh; h += 4) {
                float4 e  = *(const float4*)(pe + h);
                float4 vv = *(const float4*)(v_s + h);
                float4 p0 = *(const float4*)(pq4 + h);
                float4 p1 = *(const float4*)(pq4 + Hh + h);
                float4 p2 = *(const float4*)(pq4 + 2 * Hh + h);
                float4 p3 = *(const float4*)(pq4 + 3 * Hh + h);
                a0 = fmaf(vv.x, tanh_fast(p0.x + e.x), a0);
                a1 = fmaf(vv.x, tanh_fast(p1.x + e.x), a1);
                a2 = fmaf(vv.x, tanh_fast(p2.x + e.x), a2);
                a3 = fmaf(vv.x, tanh_fast(p3.x + e.x), a3);
                a0 = fmaf(vv.y, tanh_fast(p0.y + e.y), a0);
                a1 = fmaf(vv.y, tanh_fast(p1.y + e.y), a1);
                a2 = fmaf(vv.y, tanh_fast(p2.y + e.y), a2);
                a3 = fmaf(vv.y, tanh_fast(p3.y + e.y), a3);
                a0 = fmaf(vv.z, tanh_fast(p0.z + e.z), a0);
                a1 = fmaf(vv.z, tanh_fast(p1.z + e.z), a1);
                a2 = fmaf(vv.z, tanh_fast(p2.z + e.z), a2);
                a3 = fmaf(vv.z, tanh_fast(p3.z + e.z), a3);
                a0 = fmaf(vv.w, tanh_fast(p0.w + e.w), a0);
                a1 = fmaf(vv.w, tanh_fast(p1.w + e.w), a1);
                a2 = fmaf(vv.w, tanh_fast(p2.w + e.w), a2);
                a3 = fmaf(vv.w, tanh_fast(p3.w + e.w), a3);
            }
        }
        sv[0] = (s < len) ? a0 : NEGINF;
        sv[1] = (s < len) ? a1 : NEGINF;
        sv[2] = (s < len) ? a2 : NEGINF;
        sv[3] = (s < len) ? a3 : NEGINF;
    }

    // ---- block max (4 lanes at once) ----
    float4 m = make_float4(fmaxf(sv0[0], sv1[0]), fmaxf(sv0[1], sv1[1]),
                           fmaxf(sv0[2], sv1[2]), fmaxf(sv0[3], sv1[3]));
    #pragma unroll
    for (int o = 16; o; o >>= 1) {
        m.x = fmaxf(m.x, __shfl_xor_sync(0xffffffffu, m.x, o));
        m.y = fmaxf(m.y, __shfl_xor_sync(0xffffffffu, m.y, o));
        m.z = fmaxf(m.z, __shfl_xor_sync(0xffffffffu, m.z, o));
        m.w = fmaxf(m.w, __shfl_xor_sync(0xffffffffu, m.w, o));
    }
    if ((tid & 31) == 0) red[tid >> 5] = m;
    __syncthreads();
    if (tid == 0) {
        float4 r = red[0];
        #pragma unroll
        for (int i = 1; i < 8; ++i) {
            r.x = fmaxf(r.x, red[i].x); r.y = fmaxf(r.y, red[i].y);
            r.z = fmaxf(r.z, red[i].z); r.w = fmaxf(r.w, red[i].w);
        }
        bc = r;
    }
    __syncthreads();
    const float4 mx = bc;

    // ---- exp + block sum ----
    float e0[4], e1[4];
    e0[0] = __expf(sv0[0] - mx.x); e1[0] = __expf(sv1[0] - mx.x);
    e0[1] = __expf(sv0[1] - mx.y); e1[1] = __expf(sv1[1] - mx.y);
    e0[2] = __expf(sv0[2] - mx.z); e1[2] = __expf(sv1[2] - mx.z);
    e0[3] = __expf(sv0[3] - mx.w); e1[3] = __expf(sv1[3] - mx.w);
    float4 sm = make_float4(e0[0] + e1[0], e0[1] + e1[1], e0[2] + e1[2], e0[3] + e1[3]);
    #pragma unroll
    for (int o = 16; o; o >>= 1) {
        sm.x += __shfl_xor_sync(0xffffffffu, sm.x, o);
        sm.y += __shfl_xor_sync(0xffffffffu, sm.y, o);
        sm.z += __shfl_xor_sync(0xffffffffu, sm.z, o);
        sm.w += __shfl_xor_sync(0xffffffffu, sm.w, o);
    }
    __syncthreads();   // red reuse
    if ((tid & 31) == 0) red[tid >> 5] = sm;
    __syncthreads();
    if (tid == 0) {
        float4 r = red[0];
        #pragma unroll
        for (int i = 1; i < 8; ++i) {
            r.x += red[i].x; r.y += red[i].y; r.z += red[i].z; r.w += red[i].w;
        }
        bc = make_float4(1.f / r.x, 1.f / r.y, 1.f / r.z, 1.f / r.w);
    }
    __syncthreads();
    const float4 inv = bc;

    alp[tid][0] = e0[0] * inv.x;  alp[tid][1] = e0[1] * inv.y;
    alp[tid][2] = e0[2] * inv.z;  alp[tid][3] = e0[3] * inv.w;
    alp[tid + 256][0] = e1[0] * inv.x;  alp[tid + 256][1] = e1[1] * inv.y;
    alp[tid + 256][2] = e1[2] * inv.z;  alp[tid + 256][3] = e1[3] * inv.w;
    __syncthreads();

    // ---- context: c[tt][h] = sum_s alp[s][tt] * enc[b,s,h] ----
    const int h0 = tid;
    const int h1 = tid + 256;
    const float* eb = enc + (size_t)b * Ss * Hh;
    float c[8] = {};
    #pragma unroll 4
    for (int s = 0; s < len; ++s) {
        float4 a = *(const float4*)&alp[s][0];
        float ev0 = eb[(size_t)s * Hh + h0];
        float ev1 = eb[(size_t)s * Hh + h1];
        c[0] = fmaf(a.x, ev0, c[0]);  c[1] = fmaf(a.x, ev1, c[1]);
        c[2] = fmaf(a.y, ev0, c[2]);  c[3] = fmaf(a.y, ev1, c[3]);
        c[4] = fmaf(a.z, ev0, c[4]);  c[5] = fmaf(a.z, ev1, c[5]);
        c[6] = fmaf(a.w, ev0, c[6]);  c[7] = fmaf(a.w, ev1, c[7]);
    }
    #pragma unroll
    for (int tt = 0; tt < 4; ++tt) {
        float* crow = g_ctx + (size_t)(b * Tt + t0 + tt) * Hh;
        crow[h0] = c[2 * tt];
        crow[h1] = c[2 * tt + 1];
    }
}

// ---------------------------------------------------------------------------

extern "C" void kernel_launch(void* const* d_in, const int* in_sizes, int n_in,
                              void* d_out, int out_size)
{
    const float* query = (const float*)d_in[0];
    const float* enc   = (const float*)d_in[1];
    const int*   slen  = (const int*)d_in[2];
    const float* W_h   = (const float*)d_in[3];
    const float* W_s   = (const float*)d_in[4];
    const float* v     = (const float*)d_in[5];
    const float* W_out = (const float*)d_in[6];
    float* out = (float*)d_out;

    // Phase 1: g_pq, g_pe, g_pre in one launch (768 CTAs)
    phase1_gemm<<<768, 256>>>(query, enc, W_h, W_s, W_out);
    // Phase 2: score + softmax + context (128 CTAs)
    score_ctx_kernel<<<dim3(Tt / 4, Bb), 256>>>(enc, v, slen);
    // Phase 3: out = tanh(ctx @ W1 + pre) (128 CTAs)
    final_gemm<<<128, 256>>>(W_out, out);
}

// round 7
// speedup vs baseline: 1.9401x; 1.2520x over previous
#include <cuda_runtime.h>

#define Bb 4
#define Tt 128
#define Ss 512
#define Hh 512

// Scratch (no allocations allowed -> __device__ globals).
__device__ float  g_pq [Bb * Tt * Hh];        // query @ W_s
__device__ float  g_pe [Bb * Ss * Hh];        // encoder @ W_h
__device__ float  g_pre[Bb * Tt * Hh];        // query @ W_out[H:2H]
__device__ float  g_part[2 * Bb * Tt * Hh];   // unnormalized partial contexts (2 s-halves)
__device__ float2 g_ms [2 * Bb * Tt];         // (max, expsum) per s-half per (b,t)

__device__ __forceinline__ float tanh_fast(float x) {
    float y;
    asm("tanh.approx.f32 %0, %1;" : "=f"(y) : "f"(x));
    return y;
}

// ---------------------------------------------------------------------------
// Phase 1: three GEMMs, 64x64 tiles, BK=32, 256 threads, 4x4 micro-tile.
//   tiles [0,64):    g_pq  = query @ W_s          (512 x 512)
//   tiles [64,320):  g_pe  = enc   @ W_h          (2048 x 512)
//   tiles [320,384): g_pre = query @ W_out[H:2H]  (512 x 512)
// ---------------------------------------------------------------------------
__global__ __launch_bounds__(256) void phase1_gemm(
    const float* __restrict__ query, const float* __restrict__ enc,
    const float* __restrict__ W_h, const float* __restrict__ W_s,
    const float* __restrict__ W_out)
{
    __shared__ float As[32][68];   // transposed: As[k][m]
    __shared__ float Bs[32][68];

    int id = blockIdx.x;
    const float* A;
    const float* B;
    float* C;
    if (id < 64)       { A = query; B = W_s;            C = g_pq; }
    else if (id < 320) { A = enc;   B = W_h;            C = g_pe;  id -= 64; }
    else               { A = query; B = W_out + Hh * Hh; C = g_pre; id -= 320; }

    const int rowBase = (id >> 3) << 6;
    const int colBase = (id & 7) << 6;

    const int tid = threadIdx.x;
    const int tx = tid & 15;        // 16 col-groups of 4
    const int ty = tid >> 4;        // 16 row-groups of 4
    const int ar = tid >> 2;        // A row 0..63
    const int ak = (tid & 3) << 3;  // A k-offset 0,8,16,24
    const int bk = tid >> 3;        // B k-row 0..31
    const int bn = (tid & 7) << 3;  // B col-offset 0..56

    float acc[4][4] = {};

    for (int kt = 0; kt < Hh; kt += 32) {
        const float* ap = A + (size_t)(rowBase + ar) * Hh + kt + ak;
        float4 a0 = *(const float4*)ap;
        float4 a1 = *(const float4*)(ap + 4);
        const float* bp = B + (size_t)(kt + bk) * Hh + colBase + bn;
        float4 b0 = *(const float4*)bp;
        float4 b1 = *(const float4*)(bp + 4);
        As[ak + 0][ar] = a0.x;  As[ak + 1][ar] = a0.y;
        As[ak + 2][ar] = a0.z;  As[ak + 3][ar] = a0.w;
        As[ak + 4][ar] = a1.x;  As[ak + 5][ar] = a1.y;
        As[ak + 6][ar] = a1.z;  As[ak + 7][ar] = a1.w;
        *(float4*)&Bs[bk][bn]     = b0;
        *(float4*)&Bs[bk][bn + 4] = b1;
        __syncthreads();
        #pragma unroll
        for (int k = 0; k < 32; ++k) {
            float4 a = *(const float4*)&As[k][ty << 2];
            float4 b = *(const float4*)&Bs[k][tx << 2];
            acc[0][0] = fmaf(a.x, b.x, acc[0][0]);
            acc[0][1] = fmaf(a.x, b.y, acc[0][1]);
            acc[0][2] = fmaf(a.x, b.z, acc[0][2]);
            acc[0][3] = fmaf(a.x, b.w, acc[0][3]);
            acc[1][0] = fmaf(a.y, b.x, acc[1][0]);
            acc[1][1] = fmaf(a.y, b.y, acc[1][1]);
            acc[1][2] = fmaf(a.y, b.z, acc[1][2]);
            acc[1][3] = fmaf(a.y, b.w, acc[1][3]);
            acc[2][0] = fmaf(a.z, b.x, acc[2][0]);
            acc[2][1] = fmaf(a.z, b.y, acc[2][1]);
            acc[2][2] = fmaf(a.z, b.z, acc[2][2]);
            acc[2][3] = fmaf(a.z, b.w, acc[2][3]);
            acc[3][0] = fmaf(a.w, b.x, acc[3][0]);
            acc[3][1] = fmaf(a.w, b.y, acc[3][1]);
            acc[3][2] = fmaf(a.w, b.z, acc[3][2]);
            acc[3][3] = fmaf(a.w, b.w, acc[3][3]);
        }
        __syncthreads();
    }

    #pragma unroll
    for (int i = 0; i < 4; ++i) {
        const int r = rowBase + (ty << 2) + i;
        const int c = colBase + (tx << 2);
        *(float4*)&C[(size_t)r * Hh + c] =
            make_float4(acc[i][0], acc[i][1], acc[i][2], acc[i][3]);
    }
}

// ---------------------------------------------------------------------------
// Score + local (split-S) softmax + partial context.
// grid = (T/4, 2, B), 256 threads. Each thread owns ONE s in its half for
// scoring, then h = tid and h = tid+256 for the partial-context accumulation.
// Writes unnormalized partial context and per-(half,b,t) (max, expsum).
// ---------------------------------------------------------------------------
__global__ __launch_bounds__(256) void score_ctx_kernel(
    const float* __restrict__ enc,
    const float* __restrict__ v,
    const int* __restrict__ src_len)
{
    const int b    = blockIdx.z;
    const int half = blockIdx.y;
    const int t0   = blockIdx.x << 2;
    const int tid  = threadIdx.x;

    __shared__ float pq4[4 * Hh];
    __shared__ float v_s[Hh];
    __shared__ float alp[256][4];
    __shared__ float4 red[8];
    __shared__ float4 bc;

    const float* pqb = g_pq + (size_t)(b * Tt + t0) * Hh;
    for (int i = tid; i < 4 * Hh; i += 256) pq4[i] = pqb[i];
    for (int i = tid; i < Hh; i += 256) v_s[i] = v[i];
    __syncthreads();

    const int len = src_len[b];
    const int sBase = half << 8;
    const int s = sBase + tid;
    const bool valid = (s < len);
    const float NEGINF = __int_as_float(0xff800000);

    float sv[4] = {NEGINF, NEGINF, NEGINF, NEGINF};
    if (valid) {
        float a0 = 0.f, a1 = 0.f, a2 = 0.f, a3 = 0.f;
        const float* pe = g_pe + (size_t)(b * Ss + s) * Hh;
        #pragma unroll 2
        for (int h = 0; h < Hh; h += 4) {
            float4 e  = *(const float4*)(pe + h);
            float4 vv = *(const float4*)(v_s + h);
            float4 p0 = *(const float4*)(pq4 + h);
            float4 p1 = *(const float4*)(pq4 + Hh + h);
            float4 p2 = *(const float4*)(pq4 + 2 * Hh + h);
            float4 p3 = *(const float4*)(pq4 + 3 * Hh + h);
            a0 = fmaf(vv.x, tanh_fast(p0.x + e.x), a0);
            a1 = fmaf(vv.x, tanh_fast(p1.x + e.x), a1);
            a2 = fmaf(vv.x, tanh_fast(p2.x + e.x), a2);
            a3 = fmaf(vv.x, tanh_fast(p3.x + e.x), a3);
            a0 = fmaf(vv.y, tanh_fast(p0.y + e.y), a0);
            a1 = fmaf(vv.y, tanh_fast(p1.y + e.y), a1);
            a2 = fmaf(vv.y, tanh_fast(p2.y + e.y), a2);
            a3 = fmaf(vv.y, tanh_fast(p3.y + e.y), a3);
            a0 = fmaf(vv.z, tanh_fast(p0.z + e.z), a0);
            a1 = fmaf(vv.z, tanh_fast(p1.z + e.z), a1);
            a2 = fmaf(vv.z, tanh_fast(p2.z + e.z), a2);
            a3 = fmaf(vv.z, tanh_fast(p3.z + e.z), a3);
            a0 = fmaf(vv.w, tanh_fast(p0.w + e.w), a0);
            a1 = fmaf(vv.w, tanh_fast(p1.w + e.w), a1);
            a2 = fmaf(vv.w, tanh_fast(p2.w + e.w), a2);
            a3 = fmaf(vv.w, tanh_fast(p3.w + e.w), a3);
        }
        sv[0] = a0; sv[1] = a1; sv[2] = a2; sv[3] = a3;
    }

    // ---- local max over the 256 s of this half ----
    float4 m = make_float4(sv[0], sv[1], sv[2], sv[3]);
    #pragma unroll
    for (int o = 16; o; o >>= 1) {
        m.x = fmaxf(m.x, __shfl_xor_sync(0xffffffffu, m.x, o));
        m.y = fmaxf(m.y, __shfl_xor_sync(0xffffffffu, m.y, o));
        m.z = fmaxf(m.z, __shfl_xor_sync(0xffffffffu, m.z, o));
        m.w = fmaxf(m.w, __shfl_xor_sync(0xffffffffu, m.w, o));
    }
    if ((tid & 31) == 0) red[tid >> 5] = m;
    __syncthreads();
    if (tid == 0) {
        float4 r = red[0];
        #pragma unroll
        for (int i = 1; i < 8; ++i) {
            r.x = fmaxf(r.x, red[i].x); r.y = fmaxf(r.y, red[i].y);
            r.z = fmaxf(r.z, red[i].z); r.w = fmaxf(r.w, red[i].w);
        }
        bc = r;
    }
    __syncthreads();
    const float4 mx = bc;

    // ---- unnormalized exp + local sum ----
    float e0 = valid ? __expf(sv[0] - mx.x) : 0.f;
    float e1 = valid ? __expf(sv[1] - mx.y) : 0.f;
    float e2 = valid ? __expf(sv[2] - mx.z) : 0.f;
    float e3 = valid ? __expf(sv[3] - mx.w) : 0.f;
    float4 sm = make_float4(e0, e1, e2, e3);
    #pragma unroll
    for (int o = 16; o; o >>= 1) {
        sm.x += __shfl_xor_sync(0xffffffffu, sm.x, o);
        sm.y += __shfl_xor_sync(0xffffffffu, sm.y, o);
        sm.z += __shfl_xor_sync(0xffffffffu, sm.z, o);
        sm.w += __shfl_xor_sync(0xffffffffu, sm.w, o);
    }
    __syncthreads();   // red reuse
    if ((tid & 31) == 0) red[tid >> 5] = sm;
    __syncthreads();
    if (tid == 0) {
        float4 r = red[0];
        #pragma unroll
        for (int i = 1; i < 8; ++i) {
            r.x += red[i].x; r.y += red[i].y; r.z += red[i].z; r.w += red[i].w;
        }
        red[0] = r;   // local sums
    }
    alp[tid][0] = e0; alp[tid][1] = e1; alp[tid][2] = e2; alp[tid][3] = e3;
    __syncthreads();

    // (max, sum) for the combine step
    if (tid < 4) {
        const float* mp = (const float*)&bc;
        const float* sp = (const float*)&red[0];
        g_ms[(size_t)half * (Bb * Tt) + b * Tt + t0 + tid] =
            make_float2(mp[tid], sp[tid]);
    }

    // ---- partial context over this half's valid s ----
    int nv = len - sBase;
    if (nv > 256) nv = 256;
    const int h0 = tid;
    const int h1 = tid + 256;
    const float* eb = enc + ((size_t)b * Ss + sBase) * Hh;
    float c[8] = {};
    #pragma unroll 4
    for (int sl = 0; sl < nv; ++sl) {
        float4 a = *(const float4*)&alp[sl][0];
        float ev0 = eb[(size_t)sl * Hh + h0];
        float ev1 = eb[(size_t)sl * Hh + h1];
        c[0] = fmaf(a.x, ev0, c[0]);  c[1] = fmaf(a.x, ev1, c[1]);
        c[2] = fmaf(a.y, ev0, c[2]);  c[3] = fmaf(a.y, ev1, c[3]);
        c[4] = fmaf(a.z, ev0, c[4]);  c[5] = fmaf(a.z, ev1, c[5]);
        c[6] = fmaf(a.w, ev0, c[6]);  c[7] = fmaf(a.w, ev1, c[7]);
    }
    #pragma unroll
    for (int tt = 0; tt < 4; ++tt) {
        float* pr = g_part + ((size_t)half * (Bb * Tt) + b * Tt + t0 + tt) * Hh;
        pr[h0] = c[2 * tt];
        pr[h1] = c[2 * tt + 1];
    }
}

// ---------------------------------------------------------------------------
// Final: out = tanh( combine(g_part) @ W_out[0:H] + g_pre ).
// BM=32, BN=64, BK=32, 256 threads, 2x4 micro-tile. 128 CTAs.
// combine(A)[r][k] = p0[r][k]*w0[r] + p1[r][k]*w1[r] with softmax-merge weights.
// ---------------------------------------------------------------------------
__global__ __launch_bounds__(256) void final_gemm(
    const float* __restrict__ W_out, float* __restrict__ out)
{
    __shared__ float As[32][34];
    __shared__ float Bs[32][68];
    __shared__ float w0s[32], w1s[32];

    const int id = blockIdx.x;
    const int rowBase = (id >> 3) << 5;
    const int colBase = (id & 7) << 6;
    const int tid = threadIdx.x;

    // per-row softmax-merge weights
    if (tid < 32) {
        const int r = rowBase + tid;
        float2 a = g_ms[r];
        float2 b = g_ms[Bb * Tt + r];
        float M = fmaxf(a.x, b.x);
        float w0 = __expf(a.x - M);
        float w1 = __expf(b.x - M);
        float inv = 1.f / (a.y * w0 + b.y * w1);
        w0s[tid] = w0 * inv;
        w1s[tid] = w1 * inv;
    }
    __syncthreads();

    const int tx = tid & 15;
    const int ty = tid >> 4;
    const int ar = tid >> 3;        // A row 0..31
    const int ak = (tid & 7) << 2;  // A k-offset 0..28
    const int bk = tid >> 3;
    const int bn = (tid & 7) << 3;

    const float w0 = w0s[ar];
    const float w1 = w1s[ar];
    const float* p0 = g_part + (size_t)(rowBase + ar) * Hh;
    const float* p1 = p0 + (size_t)(Bb * Tt) * Hh;

    float acc[2][4] = {};

    for (int kt = 0; kt < Hh; kt += 32) {
        float4 u = *(const float4*)(p0 + kt + ak);
        float4 w = *(const float4*)(p1 + kt + ak);
        const float* bp = W_out + (size_t)(kt + bk) * Hh + colBase + bn;
        float4 b0 = *(const float4*)bp;
        float4 b1 = *(const float4*)(bp + 4);
        As[ak + 0][ar] = u.x * w0 + w.x * w1;
        As[ak + 1][ar] = u.y * w0 + w.y * w1;
        As[ak + 2][ar] = u.z * w0 + w.z * w1;
        As[ak + 3][ar] = u.w * w0 + w.w * w1;
        *(float4*)&Bs[bk][bn]     = b0;
        *(float4*)&Bs[bk][bn + 4] = b1;
        __syncthreads();
        #pragma unroll
        for (int k = 0; k < 32; ++k) {
            float2 a  = *(const float2*)&As[k][ty << 1];
            float4 bb = *(const float4*)&Bs[k][tx << 2];
            acc[0][0] = fmaf(a.x, bb.x, acc[0][0]);
            acc[0][1] = fmaf(a.x, bb.y, acc[0][1]);
            acc[0][2] = fmaf(a.x, bb.z, acc[0][2]);
            acc[0][3] = fmaf(a.x, bb.w, acc[0][3]);
            acc[1][0] = fmaf(a.y, bb.x, acc[1][0]);
            acc[1][1] = fmaf(a.y, bb.y, acc[1][1]);
            acc[1][2] = fmaf(a.y, bb.z, acc[1][2]);
            acc[1][3] = fmaf(a.y, bb.w, acc[1][3]);
        }
        __syncthreads();
    }

    #pragma unroll
    for (int i = 0; i < 2; ++i) {
        const int r = rowBase + (ty << 1) + i;
        const int c = colBase + (tx << 2);
        float4 pre = *(const float4*)&g_pre[(size_t)r * Hh + c];
        float4 o;
        o.x = tanh_fast(acc[i][0] + pre.x);
        o.y = tanh_fast(acc[i][1] + pre.y);
        o.z = tanh_fast(acc[i][2] + pre.z);
        o.w = tanh_fast(acc[i][3] + pre.w);
        *(float4*)&out[(size_t)r * Hh + c] = o;
    }
}

// ---------------------------------------------------------------------------

extern "C" void kernel_launch(void* const* d_in, const int* in_sizes, int n_in,
                              void* d_out, int out_size)
{
    const float* query = (const float*)d_in[0];
    const float* enc   = (const float*)d_in[1];
    const int*   slen  = (const int*)d_in[2];
    const float* W_h   = (const float*)d_in[3];
    const float* W_s   = (const float*)d_in[4];
    const float* v     = (const float*)d_in[5];
    const float* W_out = (const float*)d_in[6];
    float* out = (float*)d_out;

    // Phase 1: g_pq, g_pe, g_pre (384 CTAs)
    phase1_gemm<<<384, 256>>>(query, enc, W_h, W_s, W_out);
    // Phase 2: split-S score + local softmax + partial context (256 CTAs)
    score_ctx_kernel<<<dim3(Tt / 4, 2, Bb), 256>>>(enc, v, slen);
    // Phase 3: combine + out = tanh(ctx @ W1 + pre) (128 CTAs)
    final_gemm<<<128, 256>>>(W_out, out);
}

// round 8
// speedup vs baseline: 2.0967x; 1.0807x over previous
#include <cuda_runtime.h>

#define Bb 4
#define Tt 128
#define Ss 512
#define Hh 512
#define NCH 8      // s-chunks per batch row
#define CHS 64     // Ss / NCH

// Scratch (no allocations allowed -> __device__ globals).
__device__ float  g_pq [Bb * Tt * Hh];          // query @ W_s
__device__ float  g_pe [Bb * Ss * Hh];          // encoder @ W_h
__device__ float  g_pre[Bb * Tt * Hh];          // query @ W_out[H:2H]
__device__ float  g_part[NCH * Bb * Tt * Hh];   // unnormalized partial contexts
__device__ float2 g_ms [NCH * Bb * Tt];         // (max, expsum) per chunk per (b,t)
__device__ float  g_ctx[Bb * Tt * Hh];          // merged context

__device__ __forceinline__ float tanh_fast(float x) {
    float y;
    asm("tanh.approx.f32 %0, %1;" : "=f"(y) : "f"(x));
    return y;
}

// ---------------------------------------------------------------------------
// Phase 1: three GEMMs, 64x64 tiles, BK=32, 128 threads, 8x4 micro-tile.
//   tiles [0,64):    g_pq  = query @ W_s          (512 x 512)
//   tiles [64,320):  g_pe  = enc   @ W_h          (2048 x 512)
//   tiles [320,384): g_pre = query @ W_out[H:2H]  (512 x 512)
// ---------------------------------------------------------------------------
__global__ __launch_bounds__(128) void phase1_gemm(
    const float* __restrict__ query, const float* __restrict__ enc,
    const float* __restrict__ W_h, const float* __restrict__ W_s,
    const float* __restrict__ W_out)
{
    __shared__ float As[32][68];   // transposed: As[k][m]
    __shared__ float Bs[32][68];

    int id = blockIdx.x;
    const float* A;
    const float* B;
    float* C;
    if (id < 64)       { A = query; B = W_s;             C = g_pq; }
    else if (id < 320) { A = enc;   B = W_h;             C = g_pe;  id -= 64; }
    else               { A = query; B = W_out + Hh * Hh; C = g_pre; id -= 320; }

    const int rowBase = (id >> 3) << 6;
    const int colBase = (id & 7) << 6;

    const int tid = threadIdx.x;
    const int tx = tid & 15;            // 16 col-groups of 4
    const int ty = tid >> 4;            // 8 row-groups of 8
    const int ar = tid >> 1;            // A row 0..63
    const int ak = (tid & 1) << 4;      // A k-offset 0 or 16
    const int bk = tid >> 2;            // B k-row 0..31
    const int bn = (tid & 3) << 4;      // B col-offset 0,16,32,48

    float acc[8][4] = {};

    for (int kt = 0; kt < Hh; kt += 32) {
        const float* ap = A + (size_t)(rowBase + ar) * Hh + kt + ak;
        float4 a0 = *(const float4*)ap;
        float4 a1 = *(const float4*)(ap + 4);
        float4 a2 = *(const float4*)(ap + 8);
        float4 a3 = *(const float4*)(ap + 12);
        const float* bp = B + (size_t)(kt + bk) * Hh + colBase + bn;
        float4 b0 = *(const float4*)bp;
        float4 b1 = *(const float4*)(bp + 4);
        float4 b2 = *(const float4*)(bp + 8);
        float4 b3 = *(const float4*)(bp + 12);
        As[ak +  0][ar] = a0.x;  As[ak +  1][ar] = a0.y;
        As[ak +  2][ar] = a0.z;  As[ak +  3][ar] = a0.w;
        As[ak +  4][ar] = a1.x;  As[ak +  5][ar] = a1.y;
        As[ak +  6][ar] = a1.z;  As[ak +  7][ar] = a1.w;
        As[ak +  8][ar] = a2.x;  As[ak +  9][ar] = a2.y;
        As[ak + 10][ar] = a2.z;  As[ak + 11][ar] = a2.w;
        As[ak + 12][ar] = a3.x;  As[ak + 13][ar] = a3.y;
        As[ak + 14][ar] = a3.z;  As[ak + 15][ar] = a3.w;
        *(float4*)&Bs[bk][bn]      = b0;
        *(float4*)&Bs[bk][bn + 4]  = b1;
        *(float4*)&Bs[bk][bn + 8]  = b2;
        *(float4*)&Bs[bk][bn + 12] = b3;
        __syncthreads();
        #pragma unroll
        for (int k = 0; k < 32; ++k) {
            float4 aL = *(const float4*)&As[k][ty << 3];
            float4 aH = *(const float4*)&As[k][(ty << 3) + 4];
            float4 b  = *(const float4*)&Bs[k][tx << 2];
            acc[0][0] = fmaf(aL.x, b.x, acc[0][0]);
            acc[0][1] = fmaf(aL.x, b.y, acc[0][1]);
            acc[0][2] = fmaf(aL.x, b.z, acc[0][2]);
            acc[0][3] = fmaf(aL.x, b.w, acc[0][3]);
            acc[1][0] = fmaf(aL.y, b.x, acc[1][0]);
            acc[1][1] = fmaf(aL.y, b.y, acc[1][1]);
            acc[1][2] = fmaf(aL.y, b.z, acc[1][2]);
            acc[1][3] = fmaf(aL.y, b.w, acc[1][3]);
            acc[2][0] = fmaf(aL.z, b.x, acc[2][0]);
            acc[2][1] = fmaf(aL.z, b.y, acc[2][1]);
            acc[2][2] = fmaf(aL.z, b.z, acc[2][2]);
            acc[2][3] = fmaf(aL.z, b.w, acc[2][3]);
            acc[3][0] = fmaf(aL.w, b.x, acc[3][0]);
            acc[3][1] = fmaf(aL.w, b.y, acc[3][1]);
            acc[3][2] = fmaf(aL.w, b.z, acc[3][2]);
            acc[3][3] = fmaf(aL.w, b.w, acc[3][3]);
            acc[4][0] = fmaf(aH.x, b.x, acc[4][0]);
            acc[4][1] = fmaf(aH.x, b.y, acc[4][1]);
            acc[4][2] = fmaf(aH.x, b.z, acc[4][2]);
            acc[4][3] = fmaf(aH.x, b.w, acc[4][3]);
            acc[5][0] = fmaf(aH.y, b.x, acc[5][0]);
            acc[5][1] = fmaf(aH.y, b.y, acc[5][1]);
            acc[5][2] = fmaf(aH.y, b.z, acc[5][2]);
            acc[5][3] = fmaf(aH.y, b.w, acc[5][3]);
            acc[6][0] = fmaf(aH.z, b.x, acc[6][0]);
            acc[6][1] = fmaf(aH.z, b.y, acc[6][1]);
            acc[6][2] = fmaf(aH.z, b.z, acc[6][2]);
            acc[6][3] = fmaf(aH.z, b.w, acc[6][3]);
            acc[7][0] = fmaf(aH.w, b.x, acc[7][0]);
            acc[7][1] = fmaf(aH.w, b.y, acc[7][1]);
            acc[7][2] = fmaf(aH.w, b.z, acc[7][2]);
            acc[7][3] = fmaf(aH.w, b.w, acc[7][3]);
        }
        __syncthreads();
    }

    #pragma unroll
    for (int i = 0; i < 8; ++i) {
        const int r = rowBase + (ty << 3) + i;
        const int c = colBase + (tx << 2);
        *(float4*)&C[(size_t)r * Hh + c] =
            make_float4(acc[i][0], acc[i][1], acc[i][2], acc[i][3]);
    }
}

// ---------------------------------------------------------------------------
// Score + per-chunk softmax + partial context. 16 t x 64 s per CTA.
// grid = (T/16, NCH, B), 256 threads.
// Scoring: thread (tg = tid>>6, sl = tid&63) computes 4 t-scores for s = sl.
// Context: thread owns h = tid and h = tid+256, accumulates 16 t partials.
// ---------------------------------------------------------------------------
__global__ __launch_bounds__(256) void score_ctx_kernel(
    const float* __restrict__ enc,
    const float* __restrict__ v,
    const int* __restrict__ src_len)
{
    const int b   = blockIdx.z;
    const int ch  = blockIdx.y;
    const int t0  = blockIdx.x << 4;
    const int tid = threadIdx.x;

    __shared__ float pqs[16 * Hh];     // 32 KB
    __shared__ float v_s[Hh];
    __shared__ float alp[CHS][20];     // 16 used + pad (16B-aligned rows)
    __shared__ float red[16][17];
    __shared__ float mx[16];

    const float* pqb = g_pq + (size_t)(b * Tt + t0) * Hh;
    for (int i = tid; i < 16 * Hh / 4; i += 256)
        *(float4*)&pqs[i << 2] = *(const float4*)&pqb[i << 2];
    for (int i = tid; i < Hh; i += 256) v_s[i] = v[i];
    __syncthreads();

    const int len = src_len[b];
    const int sBase = ch * CHS;
    const int sl = tid & 63;
    const int tg = tid >> 6;           // 0..3 -> t = tg*4 + i
    const int s = sBase + sl;
    const bool valid = (s < len);
    const float NEGINF = __int_as_float(0xff800000);

    float sv[4] = {NEGINF, NEGINF, NEGINF, NEGINF};
    if (valid) {
        float a0 = 0.f, a1 = 0.f, a2 = 0.f, a3 = 0.f;
        const float* pe = g_pe + (size_t)(b * Ss + s) * Hh;
        const float* p0 = pqs + (tg << 2) * Hh;
        const float* p1 = p0 + Hh;
        const float* p2 = p0 + 2 * Hh;
        const float* p3 = p0 + 3 * Hh;
        #pragma unroll 2
        for (int h = 0; h < Hh; h += 4) {
            float4 e  = *(const float4*)(pe + h);
            float4 vv = *(const float4*)(v_s + h);
            float4 q0 = *(const float4*)(p0 + h);
            float4 q1 = *(const float4*)(p1 + h);
            float4 q2 = *(const float4*)(p2 + h);
            float4 q3 = *(const float4*)(p3 + h);
            a0 = fmaf(vv.x, tanh_fast(q0.x + e.x), a0);
            a1 = fmaf(vv.x, tanh_fast(q1.x + e.x), a1);
            a2 = fmaf(vv.x, tanh_fast(q2.x + e.x), a2);
            a3 = fmaf(vv.x, tanh_fast(q3.x + e.x), a3);
            a0 = fmaf(vv.y, tanh_fast(q0.y + e.y), a0);
            a1 = fmaf(vv.y, tanh_fast(q1.y + e.y), a1);
            a2 = fmaf(vv.y, tanh_fast(q2.y + e.y), a2);
            a3 = fmaf(vv.y, tanh_fast(q3.y + e.y), a3);
            a0 = fmaf(vv.z, tanh_fast(q0.z + e.z), a0);
            a1 = fmaf(vv.z, tanh_fast(q1.z + e.z), a1);
            a2 = fmaf(vv.z, tanh_fast(q2.z + e.z), a2);
            a3 = fmaf(vv.z, tanh_fast(q3.z + e.z), a3);
            a0 = fmaf(vv.w, tanh_fast(q0.w + e.w), a0);
            a1 = fmaf(vv.w, tanh_fast(q1.w + e.w), a1);
            a2 = fmaf(vv.w, tanh_fast(q2.w + e.w), a2);
            a3 = fmaf(vv.w, tanh_fast(q3.w + e.w), a3);
        }
        sv[0] = a0; sv[1] = a1; sv[2] = a2; sv[3] = a3;
    }

    #pragma unroll
    for (int i = 0; i < 4; ++i) alp[sl][(tg << 2) + i] = sv[i];
    __syncthreads();

    // ---- max per t over 64 s ----
    {
        const int tt = tid & 15, part = tid >> 4;
        float m0 = fmaxf(alp[(part << 2) + 0][tt], alp[(part << 2) + 1][tt]);
        float m1 = fmaxf(alp[(part << 2) + 2][tt], alp[(part << 2) + 3][tt]);
        red[part][tt] = fmaxf(m0, m1);
    }
    __syncthreads();
    if (tid < 16) {
        float m = red[0][tid];
        #pragma unroll
        for (int i = 1; i < 16; ++i) m = fmaxf(m, red[i][tid]);
        mx[tid] = m;
    }
    __syncthreads();

    // ---- exp (unnormalized) ----
    #pragma unroll
    for (int i = 0; i < 4; ++i) {
        float e = valid ? __expf(sv[i] - mx[(tg << 2) + i]) : 0.f;
        alp[sl][(tg << 2) + i] = e;
    }
    __syncthreads();

    // ---- sum per t + publish (max, sum) ----
    {
        const int tt = tid & 15, part = tid >> 4;
        red[part][tt] = alp[(part << 2) + 0][tt] + alp[(part << 2) + 1][tt]
                      + alp[(part << 2) + 2][tt] + alp[(part << 2) + 3][tt];
    }
    __syncthreads();
    if (tid < 16) {
        float sm = red[0][tid];
        #pragma unroll
        for (int i = 1; i < 16; ++i) sm += red[i][tid];
        g_ms[(size_t)ch * (Bb * Tt) + b * Tt + t0 + tid] = make_float2(mx[tid], sm);
    }

    // ---- partial context over this chunk's valid s ----
    int nv = len - sBase;
    nv = nv < 0 ? 0 : (nv > CHS ? CHS : nv);
    const int h0 = tid;
    const int h1 = tid + 256;
    const float* eb = enc + (size_t)(b * Ss + sBase) * Hh;
    float c0[16] = {};
    float c1[16] = {};
    for (int si = 0; si < nv; ++si) {
        float4 w0 = *(const float4*)&alp[si][0];
        float4 w1 = *(const float4*)&alp[si][4];
        float4 w2 = *(const float4*)&alp[si][8];
        float4 w3 = *(const float4*)&alp[si][12];
        float ev0 = eb[(size_t)si * Hh + h0];
        float ev1 = eb[(size_t)si * Hh + h1];
        c0[0]  = fmaf(w0.x, ev0, c0[0]);   c1[0]  = fmaf(w0.x, ev1, c1[0]);
        c0[1]  = fmaf(w0.y, ev0, c0[1]);   c1[1]  = fmaf(w0.y, ev1, c1[1]);
        c0[2]  = fmaf(w0.z, ev0, c0[2]);   c1[2]  = fmaf(w0.z, ev1, c1[2]);
        c0[3]  = fmaf(w0.w, ev0, c0[3]);   c1[3]  = fmaf(w0.w, ev1, c1[3]);
        c0[4]  = fmaf(w1.x, ev0, c0[4]);   c1[4]  = fmaf(w1.x, ev1, c1[4]);
        c0[5]  = fmaf(w1.y, ev0, c0[5]);   c1[5]  = fmaf(w1.y, ev1, c1[5]);
        c0[6]  = fmaf(w1.z, ev0, c0[6]);   c1[6]  = fmaf(w1.z, ev1, c1[6]);
        c0[7]  = fmaf(w1.w, ev0, c0[7]);   c1[7]  = fmaf(w1.w, ev1, c1[7]);
        c0[8]  = fmaf(w2.x, ev0, c0[8]);   c1[8]  = fmaf(w2.x, ev1, c1[8]);
        c0[9]  = fmaf(w2.y, ev0, c0[9]);   c1[9]  = fmaf(w2.y, ev1, c1[9]);
        c0[10] = fmaf(w2.z, ev0, c0[10]);  c1[10] = fmaf(w2.z, ev1, c1[10]);
        c0[11] = fmaf(w2.w, ev0, c0[11]);  c1[11] = fmaf(w2.w, ev1, c1[11]);
        c0[12] = fmaf(w3.x, ev0, c0[12]);  c1[12] = fmaf(w3.x, ev1, c1[12]);
        c0[13] = fmaf(w3.y, ev0, c0[13]);  c1[13] = fmaf(w3.y, ev1, c1[13]);
        c0[14] = fmaf(w3.z, ev0, c0[14]);  c1[14] = fmaf(w3.z, ev1, c1[14]);
        c0[15] = fmaf(w3.w, ev0, c0[15]);  c1[15] = fmaf(w3.w, ev1, c1[15]);
    }
    #pragma unroll
    for (int tt = 0; tt < 16; ++tt) {
        float* pr = g_part + ((size_t)ch * (Bb * Tt) + b * Tt + t0 + tt) * Hh;
        pr[h0] = c0[tt];
        pr[h1] = c1[tt];
    }
}

// ---------------------------------------------------------------------------
// Merge 8 partial contexts with softmax-merge weights -> g_ctx.
// grid = 256 CTAs x 256 threads; one float4 per thread.
// ---------------------------------------------------------------------------
__global__ __launch_bounds__(256) void combine_ctx()
{
    const int idx = blockIdx.x * 256 + threadIdx.x;   // 0 .. 65535
    const int r = idx >> 7;                            // row 0..511
    const int c = (idx & 127) << 2;                    // col (float)

    float m[NCH], sm[NCH];
    float M = __int_as_float(0xff800000);
    #pragma unroll
    for (int i = 0; i < NCH; ++i) {
        float2 ms = g_ms[(size_t)i * (Bb * Tt) + r];
        m[i] = ms.x; sm[i] = ms.y;
        M = fmaxf(M, m[i]);
    }
    float tot = 0.f;
    float w[NCH];
    #pragma unroll
    for (int i = 0; i < NCH; ++i) {
        w[i] = __expf(m[i] - M);
        tot = fmaf(sm[i], w[i], tot);
    }
    const float inv = 1.f / tot;

    float4 acc = make_float4(0.f, 0.f, 0.f, 0.f);
    #pragma unroll
    for (int i = 0; i < NCH; ++i) {
        const float wi = w[i] * inv;
        float4 p = *(const float4*)&g_part[((size_t)i * (Bb * Tt) + r) * Hh + c];
        acc.x = fmaf(wi, p.x, acc.x);
        acc.y = fmaf(wi, p.y, acc.y);
        acc.z = fmaf(wi, p.z, acc.z);
        acc.w = fmaf(wi, p.w, acc.w);
    }
    *(float4*)&g_ctx[(size_t)r * Hh + c] = acc;
}

// ---------------------------------------------------------------------------
// Final: out = tanh(g_ctx @ W_out[0:H] + g_pre).
// BM=32, BN=64, BK=32, 256 threads, 2x4 micro-tile. 128 CTAs.
// ---------------------------------------------------------------------------
__global__ __launch_bounds__(256) void final_gemm(
    const float* __restrict__ W_out, float* __restrict__ out)
{
    __shared__ float As[32][34];
    __shared__ float Bs[32][68];

    const int id = blockIdx.x;
    const int rowBase = (id >> 3) << 5;
    const int colBase = (id & 7) << 6;
    const int tid = threadIdx.x;

    const int tx = tid & 15;
    const int ty = tid >> 4;
    const int ar = tid >> 3;        // A row 0..31
    const int ak = (tid & 7) << 2;  // A k-offset 0..28
    const int bk = tid >> 3;
    const int bn = (tid & 7) << 3;

    const float* Ar = g_ctx + (size_t)(rowBase + ar) * Hh;
    float acc[2][4] = {};

    for (int kt = 0; kt < Hh; kt += 32) {
        float4 av = *(const float4*)(Ar + kt + ak);
        const float* bp = W_out + (size_t)(kt + bk) * Hh + colBase + bn;
        float4 b0 = *(const float4*)bp;
        float4 b1 = *(const float4*)(bp + 4);
        As[ak + 0][ar] = av.x;
        As[ak + 1][ar] = av.y;
        As[ak + 2][ar] = av.z;
        As[ak + 3][ar] = av.w;
        *(float4*)&Bs[bk][bn]     = b0;
        *(float4*)&Bs[bk][bn + 4] = b1;
        __syncthreads();
        #pragma unroll
        for (int k = 0; k < 32; ++k) {
            float2 a  = *(const float2*)&As[k][ty << 1];
            float4 bb = *(const float4*)&Bs[k][tx << 2];
            acc[0][0] = fmaf(a.x, bb.x, acc[0][0]);
            acc[0][1] = fmaf(a.x, bb.y, acc[0][1]);
            acc[0][2] = fmaf(a.x, bb.z, acc[0][2]);
            acc[0][3] = fmaf(a.x, bb.w, acc[0][3]);
            acc[1][0] = fmaf(a.y, bb.x, acc[1][0]);
            acc[1][1] = fmaf(a.y, bb.y, acc[1][1]);
            acc[1][2] = fmaf(a.y, bb.z, acc[1][2]);
            acc[1][3] = fmaf(a.y, bb.w, acc[1][3]);
        }
        __syncthreads();
    }

    #pragma unroll
    for (int i = 0; i < 2; ++i) {
        const int r = rowBase + (ty << 1) + i;
        const int c = colBase + (tx << 2);
        float4 pre = *(const float4*)&g_pre[(size_t)r * Hh + c];
        float4 o;
        o.x = tanh_fast(acc[i][0] + pre.x);
        o.y = tanh_fast(acc[i][1] + pre.y);
        o.z = tanh_fast(acc[i][2] + pre.z);
        o.w = tanh_fast(acc[i][3] + pre.w);
        *(float4*)&out[(size_t)r * Hh + c] = o;
    }
}

// ---------------------------------------------------------------------------

extern "C" void kernel_launch(void* const* d_in, const int* in_sizes, int n_in,
                              void* d_out, int out_size)
{
    const float* query = (const float*)d_in[0];
    const float* enc   = (const float*)d_in[1];
    const int*   slen  = (const int*)d_in[2];
    const float* W_h   = (const float*)d_in[3];
    const float* W_s   = (const float*)d_in[4];
    const float* v     = (const float*)d_in[5];
    const float* W_out = (const float*)d_in[6];
    float* out = (float*)d_out;

    // Phase 1: g_pq, g_pe, g_pre (384 CTAs, 128 thr)
    phase1_gemm<<<384, 128>>>(query, enc, W_h, W_s, W_out);
    // Phase 2: 16t x 64s score + per-chunk softmax + partial contexts (256 CTAs)
    score_ctx_kernel<<<dim3(Tt / 16, NCH, Bb), 256>>>(enc, v, slen);
    // Phase 2b: merge partials -> g_ctx
    combine_ctx<<<256, 256>>>();
    // Phase 3: out = tanh(ctx @ W1 + pre) (128 CTAs)
    final_gemm<<<128, 256>>>(W_out, out);
}

// round 10
// speedup vs baseline: 2.6918x; 1.2838x over previous
#include <cuda_runtime.h>
#include <cstdint>

#define Bb 4
#define Tt 128
#define Ss 512
#define Hh 512
#define NCH 8      // s-chunks per batch row
#define CHS 64     // Ss / NCH

// Scratch (no allocations allowed -> __device__ globals).
__device__ float  g_pq [Bb * Tt * Hh];          // query @ W_s
__device__ float  g_pe [Bb * Ss * Hh];          // encoder @ W_h
__device__ float  g_pre[Bb * Tt * Hh];          // query @ W_out[H:2H]
__device__ float  g_part[NCH * Bb * Tt * Hh];   // unnormalized partial contexts
__device__ float2 g_ms [NCH * Bb * Tt];         // (max, expsum) per chunk per (b,t)
__device__ float  g_ctx[Bb * Tt * Hh];          // merged context

__device__ __forceinline__ float tanh_fast(float x) {
    float y;
    asm("tanh.approx.f32 %0, %1;" : "=f"(y) : "f"(x));
    return y;
}

__device__ __forceinline__ uint32_t f2tf32(float x) {
    uint32_t u;
    asm("cvt.rna.tf32.f32 %0, %1;" : "=r"(u) : "f"(x));
    return u;
}

__device__ __forceinline__ void mma_tf32(float4& d,
    uint32_t a0, uint32_t a1, uint32_t a2, uint32_t a3,
    uint32_t b0, uint32_t b1)
{
    asm volatile(
        "mma.sync.aligned.m16n8k8.row.col.f32.tf32.tf32.f32 "
        "{%0,%1,%2,%3}, {%4,%5,%6,%7}, {%8,%9}, {%0,%1,%2,%3};"
        : "+f"(d.x), "+f"(d.y), "+f"(d.z), "+f"(d.w)
        : "r"(a0), "r"(a1), "r"(a2), "r"(a3), "r"(b0), "r"(b1));
}

// ---------------------------------------------------------------------------
// tf32 MMA GEMM tile body: BM=64, BN=64, BK=32, 256 threads (8 warps),
// warp tile 16x32 (1 m-block x 4 n-blocks of m16n8k8).
// As[m][k] padded to 36 (banks: 4*gid+ctid distinct), Bs[k][n] padded to 72
// (banks: 8*ctid+gid distinct).
// ---------------------------------------------------------------------------
__device__ __forceinline__ void mma_gemm_body(
    const float* __restrict__ A, const float* __restrict__ B, int K,
    int rowBase, int colBase,
    uint32_t (*As)[36], uint32_t (*Bs)[72], float4 acc[4])
{
    const int tid  = threadIdx.x;
    const int lane = tid & 31;
    const int warp = tid >> 5;
    const int gid  = lane >> 2;
    const int ctid = lane & 3;
    const int m0 = (warp >> 1) << 4;     // 0,16,32,48
    const int n0 = (warp & 1) << 5;      // 0,32

    const int ar = tid >> 2;             // A row 0..63
    const int ak = (tid & 3) << 3;       // A k 0,8,16,24
    const int bk = tid >> 3;             // B k 0..31
    const int bn = (tid & 7) << 3;       // B n 0,8,..,56

    for (int kt = 0; kt < K; kt += 32) {
        const float* ap = A + (size_t)(rowBase + ar) * K + kt + ak;
        float4 av0 = *(const float4*)ap;
        float4 av1 = *(const float4*)(ap + 4);
        const float* bp = B + (size_t)(kt + bk) * Hh + colBase + bn;
        float4 bv0 = *(const float4*)bp;
        float4 bv1 = *(const float4*)(bp + 4);
        As[ar][ak + 0] = f2tf32(av0.x);  As[ar][ak + 1] = f2tf32(av0.y);
        As[ar][ak + 2] = f2tf32(av0.z);  As[ar][ak + 3] = f2tf32(av0.w);
        As[ar][ak + 4] = f2tf32(av1.x);  As[ar][ak + 5] = f2tf32(av1.y);
        As[ar][ak + 6] = f2tf32(av1.z);  As[ar][ak + 7] = f2tf32(av1.w);
        Bs[bk][bn + 0] = f2tf32(bv0.x);  Bs[bk][bn + 1] = f2tf32(bv0.y);
        Bs[bk][bn + 2] = f2tf32(bv0.z);  Bs[bk][bn + 3] = f2tf32(bv0.w);
        Bs[bk][bn + 4] = f2tf32(bv1.x);  Bs[bk][bn + 5] = f2tf32(bv1.y);
        Bs[bk][bn + 6] = f2tf32(bv1.z);  Bs[bk][bn + 7] = f2tf32(bv1.w);
        __syncthreads();

        #pragma unroll
        for (int kk = 0; kk < 32; kk += 8) {
            uint32_t a0 = As[m0 + gid    ][kk + ctid];
            uint32_t a1 = As[m0 + gid + 8][kk + ctid];
            uint32_t a2 = As[m0 + gid    ][kk + ctid + 4];
            uint32_t a3 = As[m0 + gid + 8][kk + ctid + 4];
            #pragma unroll
            for (int nt = 0; nt < 4; ++nt) {
                uint32_t b0 = Bs[kk + ctid    ][n0 + (nt << 3) + gid];
                uint32_t b1 = Bs[kk + ctid + 4][n0 + (nt << 3) + gid];
                mma_tf32(acc[nt], a0, a1, a2, a3, b0, b1);
            }
        }
        __syncthreads();
    }
}

// ---------------------------------------------------------------------------
// Phase 1: three GEMMs via tf32 MMA. 384 CTAs.
//   tiles [0,64):    g_pq  = query @ W_s
//   tiles [64,320):  g_pe  = enc   @ W_h
//   tiles [320,384): g_pre = query @ W_out[H:2H]
// ---------------------------------------------------------------------------
__global__ __launch_bounds__(256) void phase1_gemm(
    const float* __restrict__ query, const float* __restrict__ enc,
    const float* __restrict__ W_h, const float* __restrict__ W_s,
    const float* __restrict__ W_out)
{
    __shared__ uint32_t As[64][36];
    __shared__ uint32_t Bs[32][72];

    int id = blockIdx.x;
    const float* A;
    const float* B;
    float* C;
    if (id < 64)       { A = query; B = W_s;             C = g_pq; }
    else if (id < 320) { A = enc;   B = W_h;             C = g_pe;  id -= 64; }
    else               { A = query; B = W_out + Hh * Hh; C = g_pre; id -= 320; }

    const int rowBase = (id >> 3) << 6;
    const int colBase = (id & 7) << 6;

    float4 acc[4] = {};
    mma_gemm_body(A, B, Hh, rowBase, colBase, As, Bs, acc);

    const int lane = threadIdx.x & 31;
    const int warp = threadIdx.x >> 5;
    const int gid  = lane >> 2;
    const int ctid = lane & 3;
    const int m0 = (warp >> 1) << 4;
    const int n0 = (warp & 1) << 5;
    #pragma unroll
    for (int nt = 0; nt < 4; ++nt) {
        const int c = colBase + n0 + (nt << 3) + (ctid << 1);
        float* r0 = &C[(size_t)(rowBase + m0 + gid) * Hh + c];
        float* r1 = &C[(size_t)(rowBase + m0 + gid + 8) * Hh + c];
        *(float2*)r0 = make_float2(acc[nt].x, acc[nt].y);
        *(float2*)r1 = make_float2(acc[nt].z, acc[nt].w);
    }
}

// ---------------------------------------------------------------------------
// Final: out = tanh(g_ctx @ W_out[0:H] + g_pre) via tf32 MMA. 64 CTAs.
// ---------------------------------------------------------------------------
__global__ __launch_bounds__(256) void final_gemm(
    const float* __restrict__ W_out, float* __restrict__ out)
{
    __shared__ uint32_t As[64][36];
    __shared__ uint32_t Bs[32][72];

    const int id = blockIdx.x;
    const int rowBase = (id >> 3) << 6;
    const int colBase = (id & 7) << 6;

    float4 acc[4] = {};
    mma_gemm_body((const float*)g_ctx, W_out, Hh, rowBase, colBase, As, Bs, acc);

    const int lane = threadIdx.x & 31;
    const int warp = threadIdx.x >> 5;
    const int gid  = lane >> 2;
    const int ctid = lane & 3;
    const int m0 = (warp >> 1) << 4;
    const int n0 = (warp & 1) << 5;
    #pragma unroll
    for (int nt = 0; nt < 4; ++nt) {
        const int c = colBase + n0 + (nt << 3) + (ctid << 1);
        const int r0i = rowBase + m0 + gid;
        const int r1i = r0i + 8;
        float2 pre0 = *(const float2*)&g_pre[(size_t)r0i * Hh + c];
        float2 pre1 = *(const float2*)&g_pre[(size_t)r1i * Hh + c];
        *(float2*)&out[(size_t)r0i * Hh + c] =
            make_float2(tanh_fast(acc[nt].x + pre0.x), tanh_fast(acc[nt].y + pre0.y));
        *(float2*)&out[(size_t)r1i * Hh + c] =
            make_float2(tanh_fast(acc[nt].z + pre1.x), tanh_fast(acc[nt].w + pre1.y));
    }
}

// ---------------------------------------------------------------------------
// Score + per-chunk softmax + partial context. 16 t x 64 s per CTA.
// grid = (T/16, NCH, B), 256 threads.  (unchanged from R8)
// ---------------------------------------------------------------------------
__global__ __launch_bounds__(256) void score_ctx_kernel(
    const float* __restrict__ enc,
    const float* __restrict__ v,
    const int* __restrict__ src_len)
{
    const int b   = blockIdx.z;
    const int ch  = blockIdx.y;
    const int t0  = blockIdx.x << 4;
    const int tid = threadIdx.x;

    __shared__ float pqs[16 * Hh];
    __shared__ float v_s[Hh];
    __shared__ float alp[CHS][20];
    __shared__ float red[16][17];
    __shared__ float mx[16];

    const float* pqb = g_pq + (size_t)(b * Tt + t0) * Hh;
    for (int i = tid; i < 16 * Hh / 4; i += 256)
        *(float4*)&pqs[i << 2] = *(const float4*)&pqb[i << 2];
    for (int i = tid; i < Hh; i += 256) v_s[i] = v[i];
    __syncthreads();

    const int len = src_len[b];
    const int sBase = ch * CHS;
    const int sl = tid & 63;
    const int tg = tid >> 6;
    const int s = sBase + sl;
    const bool valid = (s < len);
    const float NEGINF = __int_as_float(0xff800000);

    float sv[4] = {NEGINF, NEGINF, NEGINF, NEGINF};
    if (valid) {
        float a0 = 0.f, a1 = 0.f, a2 = 0.f, a3 = 0.f;
        const float* pe = g_pe + (size_t)(b * Ss + s) * Hh;
        const float* p0 = pqs + (tg << 2) * Hh;
        const float* p1 = p0 + Hh;
        const float* p2 = p0 + 2 * Hh;
        const float* p3 = p0 + 3 * Hh;
        #pragma unroll 2
        for (int h = 0; h < Hh; h += 4) {
            float4 e  = *(const float4*)(pe + h);
            float4 vv = *(const float4*)(v_s + h);
            float4 q0 = *(const float4*)(p0 + h);
            float4 q1 = *(const float4*)(p1 + h);
            float4 q2 = *(const float4*)(p2 + h);
            float4 q3 = *(const float4*)(p3 + h);
            a0 = fmaf(vv.x, tanh_fast(q0.x + e.x), a0);
            a1 = fmaf(vv.x, tanh_fast(q1.x + e.x), a1);
            a2 = fmaf(vv.x, tanh_fast(q2.x + e.x), a2);
            a3 = fmaf(vv.x, tanh_fast(q3.x + e.x), a3);
            a0 = fmaf(vv.y, tanh_fast(q0.y + e.y), a0);
            a1 = fmaf(vv.y, tanh_fast(q1.y + e.y), a1);
            a2 = fmaf(vv.y, tanh_fast(q2.y + e.y), a2);
            a3 = fmaf(vv.y, tanh_fast(q3.y + e.y), a3);
            a0 = fmaf(vv.z, tanh_fast(q0.z + e.z), a0);
            a1 = fmaf(vv.z, tanh_fast(q1.z + e.z), a1);
            a2 = fmaf(vv.z, tanh_fast(q2.z + e.z), a2);
            a3 = fmaf(vv.z, tanh_fast(q3.z + e.z), a3);
            a0 = fmaf(vv.w, tanh_fast(q0.w + e.w), a0);
            a1 = fmaf(vv.w, tanh_fast(q1.w + e.w), a1);
            a2 = fmaf(vv.w, tanh_fast(q2.w + e.w), a2);
            a3 = fmaf(vv.w, tanh_fast(q3.w + e.w), a3);
        }
        sv[0] = a0; sv[1] = a1; sv[2] = a2; sv[3] = a3;
    }

    #pragma unroll
    for (int i = 0; i < 4; ++i) alp[sl][(tg << 2) + i] = sv[i];
    __syncthreads();

    {
        const int tt = tid & 15, part = tid >> 4;
        float m0 = fmaxf(alp[(part << 2) + 0][tt], alp[(part << 2) + 1][tt]);
        float m1 = fmaxf(alp[(part << 2) + 2][tt], alp[(part << 2) + 3][tt]);
        red[part][tt] = fmaxf(m0, m1);
    }
    __syncthreads();
    if (tid < 16) {
        float m = red[0][tid];
        #pragma unroll
        for (int i = 1; i < 16; ++i) m = fmaxf(m, red[i][tid]);
        mx[tid] = m;
    }
    __syncthreads();

    #pragma unroll
    for (int i = 0; i < 4; ++i) {
        float e = valid ? __expf(sv[i] - mx[(tg << 2) + i]) : 0.f;
        alp[sl][(tg << 2) + i] = e;
    }
    __syncthreads();

    {
        const int tt = tid & 15, part = tid >> 4;
        red[part][tt] = alp[(part << 2) + 0][tt] + alp[(part << 2) + 1][tt]
                      + alp[(part << 2) + 2][tt] + alp[(part << 2) + 3][tt];
    }
    __syncthreads();
    if (tid < 16) {
        float sm = red[0][tid];
        #pragma unroll
        for (int i = 1; i < 16; ++i) sm += red[i][tid];
        g_ms[(size_t)ch * (Bb * Tt) + b * Tt + t0 + tid] = make_float2(mx[tid], sm);
    }

    int nv = len - sBase;
    nv = nv < 0 ? 0 : (nv > CHS ? CHS : nv);
    const int h0 = tid;
    const int h1 = tid + 256;
    const float* eb = enc + (size_t)(b * Ss + sBase) * Hh;
    float c0[16] = {};
    float c1[16] = {};
    for (int si = 0; si < nv; ++si) {
        float4 w0 = *(const float4*)&alp[si][0];
        float4 w1 = *(const float4*)&alp[si][4];
        float4 w2 = *(const float4*)&alp[si][8];
        float4 w3 = *(const float4*)&alp[si][12];
        float ev0 = eb[(size_t)si * Hh + h0];
        float ev1 = eb[(size_t)si * Hh + h1];
        c0[0]  = fmaf(w0.x, ev0, c0[0]);   c1[0]  = fmaf(w0.x, ev1, c1[0]);
        c0[1]  = fmaf(w0.y, ev0, c0[1]);   c1[1]  = fmaf(w0.y, ev1, c1[1]);
        c0[2]  = fmaf(w0.z, ev0, c0[2]);   c1[2]  = fmaf(w0.z, ev1, c1[2]);
        c0[3]  = fmaf(w0.w, ev0, c0[3]);   c1[3]  = fmaf(w0.w, ev1, c1[3]);
        c0[4]  = fmaf(w1.x, ev0, c0[4]);   c1[4]  = fmaf(w1.x, ev1, c1[4]);
        c0[5]  = fmaf(w1.y, ev0, c0[5]);   c1[5]  = fmaf(w1.y, ev1, c1[5]);
        c0[6]  = fmaf(w1.z, ev0, c0[6]);   c1[6]  = fmaf(w1.z, ev1, c1[6]);
        c0[7]  = fmaf(w1.w, ev0, c0[7]);   c1[7]  = fmaf(w1.w, ev1, c1[7]);
        c0[8]  = fmaf(w2.x, ev0, c0[8]);   c1[8]  = fmaf(w2.x, ev1, c1[8]);
        c0[9]  = fmaf(w2.y, ev0, c0[9]);   c1[9]  = fmaf(w2.y, ev1, c1[9]);
        c0[10] = fmaf(w2.z, ev0, c0[10]);  c1[10] = fmaf(w2.z, ev1, c1[10]);
        c0[11] = fmaf(w2.w, ev0, c0[11]);  c1[11] = fmaf(w2.w, ev1, c1[11]);
        c0[12] = fmaf(w3.x, ev0, c0[12]);  c1[12] = fmaf(w3.x, ev1, c1[12]);
        c0[13] = fmaf(w3.y, ev0, c0[13]);  c1[13] = fmaf(w3.y, ev1, c1[13]);
        c0[14] = fmaf(w3.z, ev0, c0[14]);  c1[14] = fmaf(w3.z, ev1, c1[14]);
        c0[15] = fmaf(w3.w, ev0, c0[15]);  c1[15] = fmaf(w3.w, ev1, c1[15]);
    }
    #pragma unroll
    for (int tt = 0; tt < 16; ++tt) {
        float* pr = g_part + ((size_t)ch * (Bb * Tt) + b * Tt + t0 + tt) * Hh;
        pr[h0] = c0[tt];
        pr[h1] = c1[tt];
    }
}

// ---------------------------------------------------------------------------
// Merge 8 partial contexts with softmax-merge weights -> g_ctx.
// ---------------------------------------------------------------------------
__global__ __launch_bounds__(256) void combine_ctx()
{
    const int idx = blockIdx.x * 256 + threadIdx.x;
    const int r = idx >> 7;
    const int c = (idx & 127) << 2;

    float m[NCH], sm[NCH];
    float M = __int_as_float(0xff800000);
    #pragma unroll
    for (int i = 0; i < NCH; ++i) {
        float2 ms = g_ms[(size_t)i * (Bb * Tt) + r];
        m[i] = ms.x; sm[i] = ms.y;
        M = fmaxf(M, m[i]);
    }
    float tot = 0.f;
    float w[NCH];
    #pragma unroll
    for (int i = 0; i < NCH; ++i) {
        w[i] = __expf(m[i] - M);
        tot = fmaf(sm[i], w[i], tot);
    }
    const float inv = 1.f / tot;

    float4 acc = make_float4(0.f, 0.f, 0.f, 0.f);
    #pragma unroll
    for (int i = 0; i < NCH; ++i) {
        const float wi = w[i] * inv;
        float4 p = *(const float4*)&g_part[((size_t)i * (Bb * Tt) + r) * Hh + c];
        acc.x = fmaf(wi, p.x, acc.x);
        acc.y = fmaf(wi, p.y, acc.y);
        acc.z = fmaf(wi, p.z, acc.z);
        acc.w = fmaf(wi, p.w, acc.w);
    }
    *(float4*)&g_ctx[(size_t)r * Hh + c] = acc;
}

// ---------------------------------------------------------------------------

extern "C" void kernel_launch(void* const* d_in, const int* in_sizes, int n_in,
                              void* d_out, int out_size)
{
    const float* query = (const float*)d_in[0];
    const float* enc   = (const float*)d_in[1];
    const int*   slen  = (const int*)d_in[2];
    const float* W_h   = (const float*)d_in[3];
    const float* W_s   = (const float*)d_in[4];
    const float* v     = (const float*)d_in[5];
    const float* W_out = (const float*)d_in[6];
    float* out = (float*)d_out;

    // Phase 1: g_pq, g_pe, g_pre via tf32 MMA (384 CTAs)
    phase1_gemm<<<384, 256>>>(query, enc, W_h, W_s, W_out);
    // Phase 2: 16t x 64s score + per-chunk softmax + partial contexts
    score_ctx_kernel<<<dim3(Tt / 16, NCH, Bb), 256>>>(enc, v, slen);
    // Phase 2b: merge partials -> g_ctx
    combine_ctx<<<256, 256>>>();
    // Phase 3: out = tanh(ctx @ W1 + pre) via tf32 MMA (64 CTAs)
    final_gemm<<<64, 256>>>(W_out, out);
}